// round 1
// baseline (speedup 1.0000x reference)
#include <cuda_runtime.h>
#include <cuda_bf16.h>
#include <cstdint>

// Problem shape (fixed by dataset):
//   F: [I=16, K=1024, D=64] fp32 codebooks
//   x: [I=16, B=4096, D=64] fp32 points
//   out: [I, B, D] fp32 = nearest codeword per point.
// dist-key = f_sq[k] - 2 * dot(x_b, f_k)   (x_sq constant per b -> argmin-invariant)

#define NI 16
#define NK 1024
#define NB 4096
#define ND 64

#define BTILE 128          // points per CTA
#define KTILE 128          // codewords per chunk
#define NCHUNK (NK / KTILE)
#define RS 132             // smem row stride (128 + 4 pad), floats

// scratch (device globals: allocation-free rule)
__device__ __align__(16) float g_FT[(size_t)NI * ND * NK];   // F transposed: [i][d][k], 4 MB
__device__ __align__(16) float g_fsq[NI * NK];               // ||f||^2, 64 KB

// ---------------- packed fp32x2 helpers (Blackwell FFMA2 path) ----------------
__device__ __forceinline__ void ffma2(unsigned long long& c, unsigned long long a,
                                      unsigned long long b) {
    asm("fma.rn.f32x2 %0, %1, %2, %0;" : "+l"(c) : "l"(a), "l"(b));
}
__device__ __forceinline__ unsigned long long bcast2(float v) {
    unsigned long long r;
    asm("mov.b64 %0, {%1, %1};" : "=l"(r) : "f"(v));
    return r;
}
__device__ __forceinline__ float2 unpk2(unsigned long long v) {
    float2 r;
    asm("mov.b64 {%0, %1}, %2;" : "=f"(r.x), "=f"(r.y) : "l"(v));
    return r;
}
__device__ __forceinline__ void cp_async16(void* dst, const void* src) {
    unsigned sa = (unsigned)__cvta_generic_to_shared(dst);
    asm volatile("cp.async.cg.shared.global [%0], [%1], 16;" :: "r"(sa), "l"(src));
}
__device__ __forceinline__ void cp_commit() {
    asm volatile("cp.async.commit_group;");
}
__device__ __forceinline__ void cp_wait1() {
    asm volatile("cp.async.wait_group 1;");
}
__device__ __forceinline__ void cp_wait0() {
    asm volatile("cp.async.wait_group 0;");
}

// ---------------- prep kernels ----------------
// FT[i][d][k] = F[i][k][d]
__global__ void prep_transpose(const float* __restrict__ F) {
    __shared__ float t[32][33];
    int i  = blockIdx.z;
    int kb = blockIdx.x * 32;
    int db = blockIdx.y * 32;
    int tx = threadIdx.x, ty = threadIdx.y;  // 32 x 8
    const float* src = F + ((size_t)i * NK + kb) * ND + db;
#pragma unroll
    for (int j = 0; j < 32; j += 8)
        t[ty + j][tx] = src[(size_t)(ty + j) * ND + tx];
    __syncthreads();
    float* dst = g_FT + ((size_t)i * ND + db) * NK + kb;
#pragma unroll
    for (int j = 0; j < 32; j += 8)
        dst[(size_t)(ty + j) * NK + tx] = t[tx][ty + j];
}

// fsq[i*K + k] = sum_d F[i][k][d]^2   (one warp per row)
__global__ void prep_fsq(const float* __restrict__ F) {
    int g = blockIdx.x * blockDim.x + threadIdx.x;
    int w = g >> 5, lane = g & 31;
    if (w < NI * NK) {
        float2 v = reinterpret_cast<const float2*>(F + (size_t)w * ND)[lane];
        float s = v.x * v.x + v.y * v.y;
#pragma unroll
        for (int o = 16; o; o >>= 1) s += __shfl_xor_sync(0xffffffffu, s, o);
        if (lane == 0) g_fsq[w] = s;
    }
}

// ---------------- main kernel ----------------
// grid: (NB/BTILE, NI), block 256.
// Thread (tx = tid&15 over k, ty = tid>>4 over b) owns an 8b x 8k micro-tile.
// Smem: Xs[d][b] (transposed x tile), Fs[2][d][k] (double-buffered FT tiles),
//       fsqs[2][128], sidx[128].
__global__ __launch_bounds__(256, 2)
void voro_main(const float* __restrict__ x, const float* __restrict__ F,
               float* __restrict__ out) {
    extern __shared__ float sm[];
    float* Xs   = sm;                          // ND * RS
    float* Fs   = sm + ND * RS;                // 2 * ND * RS
    float* fsqs = Fs + 2 * ND * RS;            // 2 * 128
    int*   sidx = (int*)(fsqs + 2 * KTILE);    // 128

    const int tid = threadIdx.x;
    const int tx  = tid & 15;
    const int ty  = tid >> 4;
    const int i   = blockIdx.y;
    const int b0  = blockIdx.x * BTILE;

    // ---- load + transpose x tile: Xs[d][b] ----
    const float* xi = x + ((size_t)i * NB + b0) * ND;
#pragma unroll
    for (int s = 0; s < (BTILE * ND / 4) / 256; s++) {
        int t  = tid + s * 256;
        int b  = t >> 4;        // 0..127 (16 lanes per b-row -> coalesced gmem)
        int d4 = t & 15;        // 0..15
        float4 v = *reinterpret_cast<const float4*>(xi + (size_t)b * ND + d4 * 4);
        Xs[(d4 * 4 + 0) * RS + b] = v.x;
        Xs[(d4 * 4 + 1) * RS + b] = v.y;
        Xs[(d4 * 4 + 2) * RS + b] = v.z;
        Xs[(d4 * 4 + 3) * RS + b] = v.w;
    }

    const float* FTi  = g_FT + (size_t)i * ND * NK;
    const float* fsqi = g_fsq + i * NK;

    // prefetch helper: chunk c -> buffer c&1
    auto prefetch = [&](int c) {
        int buf = c & 1;
        float* dstF = Fs + buf * (ND * RS);
        const float* srcF = FTi + c * KTILE;
#pragma unroll
        for (int s = 0; s < 8; s++) {
            int seg = tid + s * 256;   // 0..2047
            int d   = seg >> 5;        // 0..63
            int kq  = seg & 31;        // 0..31 float4-segments of a 128-wide row
            cp_async16(dstF + d * RS + kq * 4, srcF + (size_t)d * NK + kq * 4);
        }
        if (tid < 32)
            cp_async16(fsqs + buf * KTILE + tid * 4, fsqi + c * KTILE + tid * 4);
        cp_commit();
    };

    unsigned long long acc[8][4];
#pragma unroll
    for (int bb = 0; bb < 8; bb++)
#pragma unroll
        for (int j = 0; j < 4; j++) acc[bb][j] = 0ull;

    float bestd[8];
    int   besti[8];
#pragma unroll
    for (int bb = 0; bb < 8; bb++) { bestd[bb] = 3.4e38f; besti[bb] = 0; }

    prefetch(0);

    for (int c = 0; c < NCHUNK; c++) {
        if (c + 1 < NCHUNK) { prefetch(c + 1); cp_wait1(); }
        else                { cp_wait0(); }
        __syncthreads();   // buffer c ready; also protects X-tile writes on c==0

        const float* fbase = Fs + (c & 1) * (ND * RS) + tx * 8;
        const float* xbase = Xs + ty * 8;

#pragma unroll 4
        for (int d = 0; d < ND; d++) {
            // f pairs (k0,k1),(k2,k3),(k4,k5),(k6,k7): LDS.128 -> b64 pairs, no packing
            ulonglong2 fA = *reinterpret_cast<const ulonglong2*>(fbase + d * RS);
            ulonglong2 fB = *reinterpret_cast<const ulonglong2*>(fbase + d * RS + 4);
            float4 xA = *reinterpret_cast<const float4*>(xbase + d * RS);
            float4 xB = *reinterpret_cast<const float4*>(xbase + d * RS + 4);
            float xv[8] = {xA.x, xA.y, xA.z, xA.w, xB.x, xB.y, xB.z, xB.w};
#pragma unroll
            for (int bb = 0; bb < 8; bb++) {
                unsigned long long xb = bcast2(xv[bb]);
                ffma2(acc[bb][0], fA.x, xb);
                ffma2(acc[bb][1], fA.y, xb);
                ffma2(acc[bb][2], fB.x, xb);
                ffma2(acc[bb][3], fB.y, xb);
            }
        }

        // per-chunk argmin update on this thread's 8x8 tile
        const float* fsr = fsqs + (c & 1) * KTILE + tx * 8;
        float4 fa = *reinterpret_cast<const float4*>(fsr);
        float4 fb = *reinterpret_cast<const float4*>(fsr + 4);
        float fsv[8] = {fa.x, fa.y, fa.z, fa.w, fb.x, fb.y, fb.z, fb.w};
        int kb2 = c * KTILE + tx * 8;
#pragma unroll
        for (int bb = 0; bb < 8; bb++) {
#pragma unroll
            for (int j = 0; j < 4; j++) {
                float2 p = unpk2(acc[bb][j]);
                acc[bb][j] = 0ull;
                float d0 = fsv[2 * j]     - 2.0f * p.x;
                float d1 = fsv[2 * j + 1] - 2.0f * p.y;
                if (d0 < bestd[bb]) { bestd[bb] = d0; besti[bb] = kb2 + 2 * j; }
                if (d1 < bestd[bb]) { bestd[bb] = d1; besti[bb] = kb2 + 2 * j + 1; }
            }
        }
        __syncthreads();   // compute done before next prefetch overwrites buffer
    }

    // ---- cross-tx reduction (16 lanes share the same 8 b's) ----
#pragma unroll
    for (int bb = 0; bb < 8; bb++) {
        float dv = bestd[bb];
        int   iv = besti[bb];
#pragma unroll
        for (int o = 8; o >= 1; o >>= 1) {
            float od = __shfl_xor_sync(0xffffffffu, dv, o, 16);
            int   oi = __shfl_xor_sync(0xffffffffu, iv, o, 16);
            if (od < dv || (od == dv && oi < iv)) { dv = od; iv = oi; }
        }
        if (tx == 0) sidx[ty * 8 + bb] = iv;
    }
    __syncthreads();

    // ---- gather winning codewords: out[i][b][:] = F[i][sidx[b]][:] ----
    const float4* F4 = reinterpret_cast<const float4*>(F + (size_t)i * NK * ND);
    float4* O4 = reinterpret_cast<float4*>(out + ((size_t)i * NB + b0) * ND);
#pragma unroll
    for (int s = 0; s < (BTILE * (ND / 4)) / 256; s++) {
        int t = tid + s * 256;
        int b = t >> 4;       // 16 float4 per row
        int q = t & 15;
        int k = sidx[b];
        O4[(size_t)b * (ND / 4) + q] = F4[(size_t)k * (ND / 4) + q];
    }
}

// ---------------- launcher ----------------
extern "C" void kernel_launch(void* const* d_in, const int* in_sizes, int n_in,
                              void* d_out, int out_size) {
    const float* F = (const float*)d_in[0];
    const float* x = (const float*)d_in[1];
    // F has 1M elements, x has 4M — swap defensively if metadata order differs
    if (n_in >= 2 && in_sizes[0] > in_sizes[1]) {
        const float* t = F; F = x; x = t;
    }
    float* out = (float*)d_out;

    // opt-in to >48KB dynamic smem (idempotent, capture-safe host call)
    static const size_t SMEM_BYTES =
        (size_t)(ND * RS + 2 * ND * RS + 2 * KTILE + KTILE) * 4;
    cudaFuncSetAttribute(voro_main, cudaFuncAttributeMaxDynamicSharedMemorySize,
                         (int)SMEM_BYTES);

    prep_fsq<<<(NI * NK * 32) / 256, 256>>>(F);
    prep_transpose<<<dim3(NK / 32, ND / 32, NI), dim3(32, 8)>>>(F);
    voro_main<<<dim3(NB / BTILE, NI), 256, SMEM_BYTES>>>(x, F, out);
}

// round 2
// speedup vs baseline: 1.0029x; 1.0029x over previous
#include <cuda_runtime.h>
#include <cuda_bf16.h>
#include <cstdint>

// Problem shape (fixed by dataset):
//   F: [I=16, K=1024, D=64] fp32 codebooks
//   x: [I=16, B=4096, D=64] fp32 points
//   out: [I, B, D] fp32 = nearest codeword per point.
// dist-key = f_sq[k] - 2 * dot(x_b, f_k)   (x_sq constant per b -> argmin-invariant)

#define NI 16
#define NK 1024
#define NB 4096
#define ND 64

#define BTILE 128          // points per CTA
#define KTILE 128          // codewords per chunk
#define NCHUNK (NK / KTILE)
#define RS 132             // smem row stride (128 + 4 pad), floats

// scratch (device globals: allocation-free rule)
__device__ __align__(16) float g_FT[(size_t)NI * ND * NK];   // F transposed: [i][d][k], 4 MB
__device__ __align__(16) float g_fsq[NI * NK];               // ||f||^2, 64 KB

// ---------------- packed fp32x2 helpers (Blackwell FFMA2 path) ----------------
__device__ __forceinline__ void ffma2(unsigned long long& c, unsigned long long a,
                                      unsigned long long b) {
    asm("fma.rn.f32x2 %0, %1, %2, %0;" : "+l"(c) : "l"(a), "l"(b));
}
__device__ __forceinline__ unsigned long long bcast2(float v) {
    unsigned long long r;
    asm("mov.b64 %0, {%1, %1};" : "=l"(r) : "f"(v));
    return r;
}
__device__ __forceinline__ float2 unpk2(unsigned long long v) {
    float2 r;
    asm("mov.b64 {%0, %1}, %2;" : "=f"(r.x), "=f"(r.y) : "l"(v));
    return r;
}
__device__ __forceinline__ void cp_async16(void* dst, const void* src) {
    unsigned sa = (unsigned)__cvta_generic_to_shared(dst);
    asm volatile("cp.async.cg.shared.global [%0], [%1], 16;" :: "r"(sa), "l"(src));
}
__device__ __forceinline__ void cp_commit() {
    asm volatile("cp.async.commit_group;");
}
__device__ __forceinline__ void cp_wait1() {
    asm volatile("cp.async.wait_group 1;");
}
__device__ __forceinline__ void cp_wait0() {
    asm volatile("cp.async.wait_group 0;");
}

// ---------------- prep kernels ----------------
// FT[i][d][k] = F[i][k][d]
__global__ void prep_transpose(const float* __restrict__ F) {
    __shared__ float t[32][33];
    int i  = blockIdx.z;
    int kb = blockIdx.x * 32;
    int db = blockIdx.y * 32;
    int tx = threadIdx.x, ty = threadIdx.y;  // 32 x 8
    const float* src = F + ((size_t)i * NK + kb) * ND + db;
#pragma unroll
    for (int j = 0; j < 32; j += 8)
        t[ty + j][tx] = src[(size_t)(ty + j) * ND + tx];
    __syncthreads();
    float* dst = g_FT + ((size_t)i * ND + db) * NK + kb;
#pragma unroll
    for (int j = 0; j < 32; j += 8)
        dst[(size_t)(ty + j) * NK + tx] = t[tx][ty + j];
}

// fsq[i*K + k] = sum_d F[i][k][d]^2   (one warp per row)
__global__ void prep_fsq(const float* __restrict__ F) {
    int g = blockIdx.x * blockDim.x + threadIdx.x;
    int w = g >> 5, lane = g & 31;
    if (w < NI * NK) {
        float2 v = reinterpret_cast<const float2*>(F + (size_t)w * ND)[lane];
        float s = v.x * v.x + v.y * v.y;
#pragma unroll
        for (int o = 16; o; o >>= 1) s += __shfl_xor_sync(0xffffffffu, s, o);
        if (lane == 0) g_fsq[w] = s;
    }
}

// ---------------- main kernel ----------------
// grid: (NB/BTILE, NI), block 256.
// Thread (tx = tid&15 over k, ty = tid>>4 over b) owns an 8b x 8k micro-tile.
// Smem: Xs[d][b] (transposed x tile), Fs[2][d][k] (double-buffered FT tiles),
//       fsqs[2][128], sidx[128].
__global__ __launch_bounds__(256, 2)
void voro_main(const float* __restrict__ x, const float* __restrict__ F,
               float* __restrict__ out) {
    extern __shared__ float sm[];
    float* Xs   = sm;                          // ND * RS
    float* Fs   = sm + ND * RS;                // 2 * ND * RS
    float* fsqs = Fs + 2 * ND * RS;            // 2 * 128
    int*   sidx = (int*)(fsqs + 2 * KTILE);    // 128

    const int tid = threadIdx.x;
    const int tx  = tid & 15;
    const int ty  = tid >> 4;
    const int i   = blockIdx.y;
    const int b0  = blockIdx.x * BTILE;

    // ---- load + transpose x tile: Xs[d][b] ----
    const float* xi = x + ((size_t)i * NB + b0) * ND;
#pragma unroll
    for (int s = 0; s < (BTILE * ND / 4) / 256; s++) {
        int t  = tid + s * 256;
        int b  = t >> 4;        // 0..127 (16 lanes per b-row -> coalesced gmem)
        int d4 = t & 15;        // 0..15
        float4 v = *reinterpret_cast<const float4*>(xi + (size_t)b * ND + d4 * 4);
        Xs[(d4 * 4 + 0) * RS + b] = v.x;
        Xs[(d4 * 4 + 1) * RS + b] = v.y;
        Xs[(d4 * 4 + 2) * RS + b] = v.z;
        Xs[(d4 * 4 + 3) * RS + b] = v.w;
    }

    const float* FTi  = g_FT + (size_t)i * ND * NK;
    const float* fsqi = g_fsq + i * NK;

    // prefetch helper: chunk c -> buffer c&1
    auto prefetch = [&](int c) {
        int buf = c & 1;
        float* dstF = Fs + buf * (ND * RS);
        const float* srcF = FTi + c * KTILE;
#pragma unroll
        for (int s = 0; s < 8; s++) {
            int seg = tid + s * 256;   // 0..2047
            int d   = seg >> 5;        // 0..63
            int kq  = seg & 31;        // 0..31 float4-segments of a 128-wide row
            cp_async16(dstF + d * RS + kq * 4, srcF + (size_t)d * NK + kq * 4);
        }
        if (tid < 32)
            cp_async16(fsqs + buf * KTILE + tid * 4, fsqi + c * KTILE + tid * 4);
        cp_commit();
    };

    unsigned long long acc[8][4];
#pragma unroll
    for (int bb = 0; bb < 8; bb++)
#pragma unroll
        for (int j = 0; j < 4; j++) acc[bb][j] = 0ull;

    float bestd[8];
    int   besti[8];
#pragma unroll
    for (int bb = 0; bb < 8; bb++) { bestd[bb] = 3.4e38f; besti[bb] = 0; }

    prefetch(0);

    for (int c = 0; c < NCHUNK; c++) {
        if (c + 1 < NCHUNK) { prefetch(c + 1); cp_wait1(); }
        else                { cp_wait0(); }
        __syncthreads();   // buffer c ready; also protects X-tile writes on c==0

        const float* fbase = Fs + (c & 1) * (ND * RS) + tx * 8;
        const float* xbase = Xs + ty * 8;

#pragma unroll 4
        for (int d = 0; d < ND; d++) {
            // f pairs (k0,k1),(k2,k3),(k4,k5),(k6,k7): LDS.128 -> b64 pairs, no packing
            ulonglong2 fA = *reinterpret_cast<const ulonglong2*>(fbase + d * RS);
            ulonglong2 fB = *reinterpret_cast<const ulonglong2*>(fbase + d * RS + 4);
            float4 xA = *reinterpret_cast<const float4*>(xbase + d * RS);
            float4 xB = *reinterpret_cast<const float4*>(xbase + d * RS + 4);
            float xv[8] = {xA.x, xA.y, xA.z, xA.w, xB.x, xB.y, xB.z, xB.w};
#pragma unroll
            for (int bb = 0; bb < 8; bb++) {
                unsigned long long xb = bcast2(xv[bb]);
                ffma2(acc[bb][0], fA.x, xb);
                ffma2(acc[bb][1], fA.y, xb);
                ffma2(acc[bb][2], fB.x, xb);
                ffma2(acc[bb][3], fB.y, xb);
            }
        }

        // per-chunk argmin update on this thread's 8x8 tile
        const float* fsr = fsqs + (c & 1) * KTILE + tx * 8;
        float4 fa = *reinterpret_cast<const float4*>(fsr);
        float4 fb = *reinterpret_cast<const float4*>(fsr + 4);
        float fsv[8] = {fa.x, fa.y, fa.z, fa.w, fb.x, fb.y, fb.z, fb.w};
        int kb2 = c * KTILE + tx * 8;
#pragma unroll
        for (int bb = 0; bb < 8; bb++) {
#pragma unroll
            for (int j = 0; j < 4; j++) {
                float2 p = unpk2(acc[bb][j]);
                acc[bb][j] = 0ull;
                float d0 = fsv[2 * j]     - 2.0f * p.x;
                float d1 = fsv[2 * j + 1] - 2.0f * p.y;
                if (d0 < bestd[bb]) { bestd[bb] = d0; besti[bb] = kb2 + 2 * j; }
                if (d1 < bestd[bb]) { bestd[bb] = d1; besti[bb] = kb2 + 2 * j + 1; }
            }
        }
        __syncthreads();   // compute done before next prefetch overwrites buffer
    }

    // ---- cross-tx reduction (16 lanes share the same 8 b's) ----
#pragma unroll
    for (int bb = 0; bb < 8; bb++) {
        float dv = bestd[bb];
        int   iv = besti[bb];
#pragma unroll
        for (int o = 8; o >= 1; o >>= 1) {
            float od = __shfl_xor_sync(0xffffffffu, dv, o, 16);
            int   oi = __shfl_xor_sync(0xffffffffu, iv, o, 16);
            if (od < dv || (od == dv && oi < iv)) { dv = od; iv = oi; }
        }
        if (tx == 0) sidx[ty * 8 + bb] = iv;
    }
    __syncthreads();

    // ---- gather winning codewords: out[i][b][:] = F[i][sidx[b]][:] ----
    const float4* F4 = reinterpret_cast<const float4*>(F + (size_t)i * NK * ND);
    float4* O4 = reinterpret_cast<float4*>(out + ((size_t)i * NB + b0) * ND);
#pragma unroll
    for (int s = 0; s < (BTILE * (ND / 4)) / 256; s++) {
        int t = tid + s * 256;
        int b = t >> 4;       // 16 float4 per row
        int q = t & 15;
        int k = sidx[b];
        O4[(size_t)b * (ND / 4) + q] = F4[(size_t)k * (ND / 4) + q];
    }
}

// ---------------- launcher ----------------
extern "C" void kernel_launch(void* const* d_in, const int* in_sizes, int n_in,
                              void* d_out, int out_size) {
    const float* F = (const float*)d_in[0];
    const float* x = (const float*)d_in[1];
    // F has 1M elements, x has 4M — swap defensively if metadata order differs
    if (n_in >= 2 && in_sizes[0] > in_sizes[1]) {
        const float* t = F; F = x; x = t;
    }
    float* out = (float*)d_out;

    // opt-in to >48KB dynamic smem (idempotent, capture-safe host call)
    static const size_t SMEM_BYTES =
        (size_t)(ND * RS + 2 * ND * RS + 2 * KTILE + KTILE) * 4;
    cudaFuncSetAttribute(voro_main, cudaFuncAttributeMaxDynamicSharedMemorySize,
                         (int)SMEM_BYTES);

    prep_fsq<<<(NI * NK * 32) / 256, 256>>>(F);
    prep_transpose<<<dim3(NK / 32, ND / 32, NI), dim3(32, 8)>>>(F);
    voro_main<<<dim3(NB / BTILE, NI), 256, SMEM_BYTES>>>(x, F, out);
}